// round 8
// baseline (speedup 1.0000x reference)
#include <cuda_runtime.h>

#define MQ 32
#define NG 256
#define DD 128

__device__ __forceinline__ unsigned long long pack2(float lo, float hi) {
    unsigned long long r;
    asm("mov.b64 %0, {%1, %2};" : "=l"(r) : "f"(lo), "f"(hi));
    return r;
}
__device__ __forceinline__ unsigned long long fma2(unsigned long long a,
                                                   unsigned long long b,
                                                   unsigned long long c) {
    unsigned long long d;
    asm("fma.rn.f32x2 %0, %1, %2, %3;" : "=l"(d) : "l"(a), "l"(b), "l"(c));
    return d;
}
__device__ __forceinline__ void unpack2(unsigned long long v, float& lo, float& hi) {
    asm("mov.b64 {%0, %1}, %2;" : "=f"(lo), "=f"(hi) : "l"(v));
}

// Block = one gallery item j, 1024 threads. Thread owns a 4x4 tile:
// a-rows 4*(t>>5).. (warp-uniform -> ua LDS.128 is a broadcast),
// b-cols 4*(t&31).. (lanes cover the 512B row contiguously -> conflict-free).
// 32 regs/thread, 2 blocks/SM -> ~16 warps/SMSP resident (2x Round 7).
// pen(i,j) = 16384*ze + 0.5*( su_i^2 - sumMp - 16384*ze + sum|t'| ),
// t' = ua*ub - Mp - ze.
__global__ __launch_bounds__(1024, 2)
void jacc_pen_kernel(const float* __restrict__ qf,
                     const float* __restrict__ x,
                     const float* __restrict__ Mp,
                     const float* __restrict__ zep,
                     float* __restrict__ out) {
    const int j = blockIdx.x;
    const int t = threadIdx.x;
    const float ze = *zep;

    __shared__ __align__(16) float u_s[MQ][DD];   // 16 KB
    __shared__ float part_s[MQ][128];             // 16 KB: oct-reduced partials
    __shared__ float su_s[MQ], sv_s[MQ];
    __shared__ float sMw_s[32];

    const float* __restrict__ xj = x + j * DD;

    // ---- u[i][d] = max(qf[i][d], x[j][d]) : 4096 / 1024 threads ----
    #pragma unroll
    for (int k = 0; k < (MQ * DD) / 1024; ++k) {
        int e = t + 1024 * k;
        int i = e >> 7;
        int d = e & (DD - 1);
        u_s[i][d] = fmaxf(qf[e], xj[d]);
    }

    // ---- dist0 row sums: warp w handles query i=w, lane covers 4 d's ----
    {
        int i = t >> 5;
        int l = t & 31;
        float4 q4 = *reinterpret_cast<const float4*>(qf + i * DD + l * 4);
        float4 x4 = *reinterpret_cast<const float4*>(xj + l * 4);
        float su = (fmaxf(q4.x, x4.x) + fmaxf(q4.y, x4.y))
                 + (fmaxf(q4.z, x4.z) + fmaxf(q4.w, x4.w));
        float sv = (fminf(q4.x, x4.x) + fminf(q4.y, x4.y))
                 + (fminf(q4.z, x4.z) + fminf(q4.w, x4.w));
        #pragma unroll
        for (int off = 16; off >= 1; off >>= 1) {
            su += __shfl_xor_sync(0xffffffffu, su, off);
            sv += __shfl_xor_sync(0xffffffffu, sv, off);
        }
        if (l == 0) { su_s[i] = su; sv_s[i] = sv; }
    }

    // ---- Load 4x4 Mp tile, pack (-Mp - ze) as f32x2; warp-reduce tile sum ----
    const int a0 = (t >> 5) * 4;
    const int b0 = (t & 31) * 4;
    unsigned long long nM2[4][2];
    {
        float msum = 0.0f;
        #pragma unroll
        for (int aa = 0; aa < 4; ++aa) {
            float4 m0 = *reinterpret_cast<const float4*>(Mp + (a0 + aa) * DD + b0);
            msum += (m0.x + m0.y) + (m0.z + m0.w);
            nM2[aa][0] = pack2(-m0.x - ze, -m0.y - ze);
            nM2[aa][1] = pack2(-m0.z - ze, -m0.w - ze);
        }
        #pragma unroll
        for (int off = 16; off >= 1; off >>= 1)
            msum += __shfl_xor_sync(0xffffffffu, msum, off);
        if ((t & 31) == 0) sMw_s[t >> 5] = msum;
    }

    __syncthreads();

    // ---- Hot loop: sum |ua*ub - Mp - ze| over the 4x4 tile, per query i ----
    const float* ua_p = &u_s[0][a0];   // warp-broadcast LDS.128
    const float* ub_p = &u_s[0][b0];   // contiguous across lanes, conflict-free
    float* st_p = &part_s[0][t >> 3];
    #pragma unroll 1
    for (int i = 0; i < MQ; ++i) {
        float4 va = *reinterpret_cast<const float4*>(ua_p);
        ulonglong2 c0 = *reinterpret_cast<const ulonglong2*>(ub_p);
        unsigned long long ub2[2] = {c0.x, c0.y};
        float ua[4] = {va.x, va.y, va.z, va.w};

        float acc[4] = {0.0f, 0.0f, 0.0f, 0.0f};
        #pragma unroll
        for (int aa = 0; aa < 4; ++aa) {
            unsigned long long ua2 = pack2(ua[aa], ua[aa]);
            #pragma unroll
            for (int bp = 0; bp < 2; ++bp) {
                float lo, hi;
                unpack2(fma2(ua2, ub2[bp], nM2[aa][bp]), lo, hi);
                acc[2 * bp]     += fabsf(lo);   // FADD with |src| modifier
                acc[2 * bp + 1] += fabsf(hi);
            }
        }
        float w = (acc[0] + acc[1]) + (acc[2] + acc[3]);

        // oct reduce (3 shfl, width 8), predicated STS
        w += __shfl_down_sync(0xffffffffu, w, 4, 8);
        w += __shfl_down_sync(0xffffffffu, w, 2, 8);
        w += __shfl_down_sync(0xffffffffu, w, 1, 8);
        if ((t & 7) == 0) *st_p = w;

        ua_p += DD;
        ub_p += DD;
        st_p += 128;
    }

    __syncthreads();

    // ---- Final phase: warp w finishes query i=w ----
    {
        const int w = t >> 5;
        const int l = t & 31;

        float sm = sMw_s[l];            // 32 per-warp Mp sums
        float p  = (part_s[w][l]      + part_s[w][l + 32])
                 + (part_s[w][l + 64] + part_s[w][l + 96]);
        #pragma unroll
        for (int off = 16; off >= 1; off >>= 1) {
            sm += __shfl_xor_sync(0xffffffffu, sm, off);
            p  += __shfl_xor_sync(0xffffffffu, p, off);
        }
        if (l == 0) {
            float su = su_s[w];
            const float NE = (float)(DD * DD);  // 16384
            float pen = NE * ze + 0.5f * ((su * su - sm - NE * ze) + p);
            out[w * NG + j] = sv_s[w] / su - 0.001f * pen;
        }
    }
}

extern "C" void kernel_launch(void* const* d_in, const int* in_sizes, int n_in,
                              void* d_out, int out_size) {
    const float* qf = (const float*)d_in[0];   // (32, 128)
    const float* x  = (const float*)d_in[1];   // (256, 128)
    const float* Mp = (const float*)d_in[2];   // (128, 128)
    const float* ze = (const float*)d_in[3];   // scalar
    float* out = (float*)d_out;                // (32, 256)
    (void)in_sizes; (void)n_in; (void)out_size;

    jacc_pen_kernel<<<NG, 1024>>>(qf, x, Mp, ze, out);
}

// round 10
// speedup vs baseline: 1.3111x; 1.3111x over previous
#include <cuda_runtime.h>

#define MQ 32
#define NG 256
#define DD 128
#define QH 16   // queries per block (half of MQ)

__device__ __forceinline__ unsigned long long pack2(float lo, float hi) {
    unsigned long long r;
    asm("mov.b64 %0, {%1, %2};" : "=l"(r) : "f"(lo), "f"(hi));
    return r;
}
__device__ __forceinline__ unsigned long long fma2(unsigned long long a,
                                                   unsigned long long b,
                                                   unsigned long long c) {
    unsigned long long d;
    asm("fma.rn.f32x2 %0, %1, %2, %3;" : "=l"(d) : "l"(a), "l"(b), "l"(c));
    return d;
}
__device__ __forceinline__ void unpack2(unsigned long long v, float& lo, float& hi) {
    asm("mov.b64 {%0, %1}, %2;" : "=f"(lo), "=f"(hi) : "l"(v));
}

// Block = (gallery item j, query half): grid 512 x 512 threads for SM load
// balance (T_block halves; 296+216 wave structure beats 256 x double-length).
// Thread owns a-rows (t>>4)*4..+3 and b-cols {4m..4m+3, 64+4m..64+4m+3}
// (conflict-free LDS.128). Inner: FFMA2 + FADD-with-|src| (best known form).
// pen(i,j) = 16384*ze + 0.5*( su_i^2 - sumMp - 16384*ze + sum|t'| ),
// t' = ua*ub - Mp - ze.
__global__ __launch_bounds__(512, 2)
void jacc_pen_kernel(const float* __restrict__ qf,
                     const float* __restrict__ x,
                     const float* __restrict__ Mp,
                     const float* __restrict__ zep,
                     float* __restrict__ out) {
    const int j     = blockIdx.x >> 1;
    const int ibase = (blockIdx.x & 1) * QH;
    const int t = threadIdx.x;
    const float ze = *zep;

    __shared__ __align__(16) float u_s[QH][DD];   // 8 KB
    __shared__ float part_s[QH][128];             // 8 KB
    __shared__ float su_s[QH], sv_s[QH];
    __shared__ float sMw_s[16];

    const float* __restrict__ xj = x + j * DD;

    // ---- u[i][d] = max(qf[ibase+i][d], x[j][d]) : 2048 elems / 512 thr ----
    #pragma unroll
    for (int k = 0; k < (QH * DD) / 512; ++k) {
        int e = t + 512 * k;
        int i = e >> 7;
        int d = e & (DD - 1);
        u_s[i][d] = fmaxf(qf[(ibase + i) * DD + d], xj[d]);
    }

    // ---- dist0 row sums: warp w handles query w (16 warps, 16 queries) ----
    {
        int i = t >> 5;
        int l = t & 31;
        float4 q4 = *reinterpret_cast<const float4*>(qf + (ibase + i) * DD + l * 4);
        float4 x4 = *reinterpret_cast<const float4*>(xj + l * 4);
        float su = (fmaxf(q4.x, x4.x) + fmaxf(q4.y, x4.y))
                 + (fmaxf(q4.z, x4.z) + fmaxf(q4.w, x4.w));
        float sv = (fminf(q4.x, x4.x) + fminf(q4.y, x4.y))
                 + (fminf(q4.z, x4.z) + fminf(q4.w, x4.w));
        #pragma unroll
        for (int off = 16; off >= 1; off >>= 1) {
            su += __shfl_xor_sync(0xffffffffu, su, off);
            sv += __shfl_xor_sync(0xffffffffu, sv, off);
        }
        if (l == 0) { su_s[i] = su; sv_s[i] = sv; }
    }

    // ---- Load 4x8 Mp tile, pack (-Mp - ze) as f32x2; warp-reduce tile sum ----
    const int a0 = (t >> 4) * 4;
    const int m  = t & 15;
    const int bA = 4 * m;
    const int bB = 64 + 4 * m;
    unsigned long long nM2[4][4];
    {
        float msum = 0.0f;
        #pragma unroll
        for (int aa = 0; aa < 4; ++aa) {
            float4 m0 = *reinterpret_cast<const float4*>(Mp + (a0 + aa) * DD + bA);
            float4 m1 = *reinterpret_cast<const float4*>(Mp + (a0 + aa) * DD + bB);
            msum += ((m0.x + m0.y) + (m0.z + m0.w)) + ((m1.x + m1.y) + (m1.z + m1.w));
            nM2[aa][0] = pack2(-m0.x - ze, -m0.y - ze);
            nM2[aa][1] = pack2(-m0.z - ze, -m0.w - ze);
            nM2[aa][2] = pack2(-m1.x - ze, -m1.y - ze);
            nM2[aa][3] = pack2(-m1.z - ze, -m1.w - ze);
        }
        #pragma unroll
        for (int off = 16; off >= 1; off >>= 1)
            msum += __shfl_xor_sync(0xffffffffu, msum, off);
        if ((t & 31) == 0) sMw_s[t >> 5] = msum;
    }

    __syncthreads();

    // ---- Hot loop: sum |ua*ub - Mp - ze|, 4 queries per pass ----
    const float* ua_p = &u_s[0][a0];
    const float* ub_p = &u_s[0][bA];
    float* st_p = &part_s[0][t >> 2];
    #pragma unroll 1
    for (int ig = 0; ig < QH; ig += 4) {
        float w[4];
        #pragma unroll
        for (int s = 0; s < 4; ++s) {
            const float* uap = ua_p + s * DD;
            const float* ubp = ub_p + s * DD;
            float4 va = *reinterpret_cast<const float4*>(uap);
            ulonglong2 c0 = *reinterpret_cast<const ulonglong2*>(ubp);
            ulonglong2 c1 = *reinterpret_cast<const ulonglong2*>(ubp + 64);
            unsigned long long ub2[4] = {c0.x, c0.y, c1.x, c1.y};
            float ua[4] = {va.x, va.y, va.z, va.w};

            float acc[4] = {0.0f, 0.0f, 0.0f, 0.0f};
            #pragma unroll
            for (int aa = 0; aa < 4; ++aa) {
                unsigned long long ua2 = pack2(ua[aa], ua[aa]);
                #pragma unroll
                for (int bpp = 0; bpp < 4; ++bpp) {
                    float lo, hi;
                    unpack2(fma2(ua2, ub2[bpp], nM2[aa][bpp]), lo, hi);
                    acc[bpp] += fabsf(lo);              // FADD with |src| modifier
                    acc[(bpp + 2) & 3] += fabsf(hi);
                }
            }
            w[s] = (acc[0] + acc[1]) + (acc[2] + acc[3]);
        }

        // 4 independent quad reductions (overlapping shfl chains)
        #pragma unroll
        for (int s = 0; s < 4; ++s)
            w[s] += __shfl_down_sync(0xffffffffu, w[s], 2, 4);
        #pragma unroll
        for (int s = 0; s < 4; ++s)
            w[s] += __shfl_down_sync(0xffffffffu, w[s], 1, 4);
        if ((t & 3) == 0) {
            #pragma unroll
            for (int s = 0; s < 4; ++s)
                st_p[s * 128] = w[s];
        }

        ua_p += 4 * DD;
        ub_p += 4 * DD;
        st_p += 4 * 128;
    }

    __syncthreads();

    // ---- Final phase: warp w finishes query w ----
    {
        const int w = t >> 5;
        const int l = t & 31;

        float sm = 0.0f;
        #pragma unroll
        for (int k = 0; k < 16; ++k) sm += sMw_s[k];

        float p = (part_s[w][l]      + part_s[w][l + 32])
                + (part_s[w][l + 64] + part_s[w][l + 96]);
        #pragma unroll
        for (int off = 16; off >= 1; off >>= 1)
            p += __shfl_xor_sync(0xffffffffu, p, off);
        if (l == 0) {
            float su = su_s[w];
            const float NE = (float)(DD * DD);  // 16384
            float pen = NE * ze + 0.5f * ((su * su - sm - NE * ze) + p);
            out[(ibase + w) * NG + j] = sv_s[w] / su - 0.001f * pen;
        }
    }
}

extern "C" void kernel_launch(void* const* d_in, const int* in_sizes, int n_in,
                              void* d_out, int out_size) {
    const float* qf = (const float*)d_in[0];   // (32, 128)
    const float* x  = (const float*)d_in[1];   // (256, 128)
    const float* Mp = (const float*)d_in[2];   // (128, 128)
    const float* ze = (const float*)d_in[3];   // scalar
    float* out = (float*)d_out;                // (32, 256)
    (void)in_sizes; (void)n_in; (void)out_size;

    jacc_pen_kernel<<<2 * NG, 512>>>(qf, x, Mp, ze, out);
}